// round 7
// baseline (speedup 1.0000x reference)
#include <cuda_runtime.h>
#include <cuda_bf16.h>
#include <cstdint>

#define BATCH 8
#define SEQ 512
#define DM 512
#define NELEM (BATCH*SEQ*DM)

// ============================ scratch (bf16 hi/lo splits) ============================
__device__ __align__(16) __nv_bfloat16 g_Qhi[NELEM];
__device__ __align__(16) __nv_bfloat16 g_Qlo[NELEM];
__device__ __align__(16) __nv_bfloat16 g_QRhi[NELEM];
__device__ __align__(16) __nv_bfloat16 g_QRlo[NELEM];
__device__ __align__(16) __nv_bfloat16 g_Khi[NELEM];
__device__ __align__(16) __nv_bfloat16 g_Klo[NELEM];
__device__ __align__(16) __nv_bfloat16 g_Ethi[DM*DM];
__device__ __align__(16) __nv_bfloat16 g_Etlo[DM*DM];

__device__ __forceinline__ void split_bf16(float x, __nv_bfloat16& h, __nv_bfloat16& l) {
    h = __float2bfloat16(x);
    l = __float2bfloat16(x - __bfloat162float(h));
}

__device__ __forceinline__ uint32_t smem_u32(const void* p) {
    uint32_t a;
    asm("{ .reg .u64 t; cvta.to.shared.u64 t, %1; cvt.u32.u64 %0, t; }" : "=r"(a) : "l"(p));
    return a;
}

// ============================ fused prep kernel ============================
// blocks [0, 4096): Q rows (split + reversal); [4096, 6144): K split; [6144, 6400): E transpose-split
#define QBLOCKS (BATCH*SEQ)
#define KBLOCKS 2048
#define EBLOCKS 256

__global__ void prep_all_kernel(const float* __restrict__ q,
                                const float* __restrict__ k,
                                const float* __restrict__ e) {
    __shared__ float sh[32 * 33 + 128];   // reused: Q row(512)+red(128) | E tile(1056)
    int bid = blockIdx.x;
    int t = threadIdx.x;                  // 128 threads

    if (bid < QBLOCKS) {
        float* row = sh;                  // 512
        float* red = sh + 512;            // 128
        int i = bid & (SEQ - 1);
        const float4* src = reinterpret_cast<const float4*>(q + (size_t)bid * DM);
        reinterpret_cast<float4*>(row)[t] = src[t];
        __syncthreads();

        float p = 0.f;
        #pragma unroll
        for (int j = t; j < DM; j += 128)
            if (j >= i) p += row[j];
        red[t] = p;
        __syncthreads();
        #pragma unroll
        for (int s = 64; s > 0; s >>= 1) {
            if (t < s) red[t] += red[t + s];
            __syncthreads();
        }
        float suf = red[0];

        size_t base = (size_t)bid * DM;
        #pragma unroll
        for (int d = t; d < DM; d += 128) {
            float x = row[d];
            split_bf16(x, g_Qhi[base + d], g_Qlo[base + d]);
            float r = (d == 0) ? suf : ((d <= i) ? row[i - d] : 0.f);
            split_bf16(r, g_QRhi[base + d], g_QRlo[base + d]);
        }
    } else if (bid < QBLOCKS + KBLOCKS) {
        int idx = (bid - QBLOCKS) * 128 + t;
        int n4 = NELEM / 4;
        int stride = KBLOCKS * 128;
        for (int j = idx; j < n4; j += stride) {
            float4 v = reinterpret_cast<const float4*>(k)[j];
            __nv_bfloat16 h[4], l[4];
            split_bf16(v.x, h[0], l[0]);
            split_bf16(v.y, h[1], l[1]);
            split_bf16(v.z, h[2], l[2]);
            split_bf16(v.w, h[3], l[3]);
            reinterpret_cast<uint2*>(g_Khi)[j] = *reinterpret_cast<uint2*>(h);
            reinterpret_cast<uint2*>(g_Klo)[j] = *reinterpret_cast<uint2*>(l);
        }
    } else {
        float (*tile)[33] = reinterpret_cast<float(*)[33]>(sh);
        int eb = bid - QBLOCKS - KBLOCKS;
        int bx = eb & 15, by = eb >> 4;
        int tx = t & 31, j0 = t >> 5;     // 4 row-groups
        #pragma unroll
        for (int j = j0; j < 32; j += 4)
            tile[j][tx] = e[(size_t)(by * 32 + j) * DM + bx * 32 + tx];
        __syncthreads();
        #pragma unroll
        for (int j = j0; j < 32; j += 4) {
            size_t o = (size_t)(bx * 32 + j) * DM + by * 32 + tx;
            split_bf16(tile[tx][j], g_Ethi[o], g_Etlo[o]);
        }
    }
}

// ============================ main GEMM (mma.sync bf16, term-shared) ============================
// out[b,i,n] = Qhi.Khi + Qhi.Klo + Qlo.Khi  +  QRhi.Ethi + QRhi.Etlo + QRlo.Ethi
// Stage holds {Ahi, Alo, Bhi, Blo} for one 64-wide K chunk.
// Warp-groups process k16 steps in rotated order so LSU (ldmatrix) bursts of half
// the warps overlap MMA bursts of the other half within each SMSP.

#define BM 128
#define BN 64
#define BK 64
#define AT_B (BM * BK * 2)                  // 16384 per A tile
#define BT_B (BN * BK * 2)                  // 8192 per B tile
#define STAGE_B (2 * AT_B + 2 * BT_B)       // 49152
#define SMEM_TOTAL (2 * STAGE_B)            // 98304 (2 stages), 2 CTAs/SM
#define NCHUNK 16                           // 2 passes * 8 chunks of K=64

#define OFF_AH 0
#define OFF_AL AT_B
#define OFF_BH (2 * AT_B)
#define OFF_BL (2 * AT_B + BT_B)

__device__ __forceinline__ uint32_t sw_off(int row, int kk) {
    return (uint32_t)(row * 128 + (((kk >> 3) ^ (row & 7)) << 4) + ((kk & 7) << 1));
}

__device__ __forceinline__ void cp_async16(uint32_t saddr, const void* gaddr) {
    asm volatile("cp.async.cg.shared.global [%0], [%1], 16;" :: "r"(saddr), "l"(gaddr));
}

__device__ __forceinline__ void ldmatrix_x4(uint32_t& r0, uint32_t& r1, uint32_t& r2,
                                            uint32_t& r3, uint32_t addr) {
    asm volatile("ldmatrix.sync.aligned.m8n8.x4.shared.b16 {%0,%1,%2,%3}, [%4];"
                 : "=r"(r0), "=r"(r1), "=r"(r2), "=r"(r3) : "r"(addr));
}

__device__ __forceinline__ void mma16816(float* c, const uint32_t* a, uint32_t b0, uint32_t b1) {
    asm volatile(
        "mma.sync.aligned.m16n8k16.row.col.f32.bf16.bf16.f32 "
        "{%0,%1,%2,%3}, {%4,%5,%6,%7}, {%8,%9}, {%0,%1,%2,%3};"
        : "+f"(c[0]), "+f"(c[1]), "+f"(c[2]), "+f"(c[3])
        : "r"(a[0]), "r"(a[1]), "r"(a[2]), "r"(a[3]), "r"(b0), "r"(b1));
}

__global__ __launch_bounds__(256, 2) void rel_gemm_kernel(float* __restrict__ out) {
    extern __shared__ char smem[];
    uint32_t sb = smem_u32(smem);

    int tid = threadIdx.x;
    int lane = tid & 31, wid = tid >> 5;
    int wm = wid & 3, wn = wid >> 2;          // 4 m-warps x 2 n-warps, warp tile 32x32
    int kphase = (wid >> 2) << 1;             // warps 0-3: phase 0; warps 4-7: phase 2
    int n0 = blockIdx.x * BN;
    int m0 = blockIdx.y * BM;
    int b  = blockIdx.z;
    size_t boff = (size_t)b * SEQ * DM;

    const __nv_bfloat16* AH[2] = { g_Qhi + boff, g_QRhi + boff };
    const __nv_bfloat16* AL[2] = { g_Qlo + boff, g_QRlo + boff };
    const __nv_bfloat16* BH[2] = { g_Khi + boff, g_Ethi };
    const __nv_bfloat16* BL[2] = { g_Klo + boff, g_Etlo };

    float acc[2][4][4];
    #pragma unroll
    for (int mi = 0; mi < 2; mi++)
        #pragma unroll
        for (int ni = 0; ni < 4; ni++)
            #pragma unroll
            for (int j = 0; j < 4; j++) acc[mi][ni][j] = 0.f;

    auto load_chunk = [&](int it, int buf) {
        int pass = it >> 3, kc = it & 7;
        const __nv_bfloat16* ah = AH[pass] + (size_t)m0 * DM + kc * BK;
        const __nv_bfloat16* al = AL[pass] + (size_t)m0 * DM + kc * BK;
        const __nv_bfloat16* bh = BH[pass] + (size_t)n0 * DM + kc * BK;
        const __nv_bfloat16* bl = BL[pass] + (size_t)n0 * DM + kc * BK;
        uint32_t st = sb + buf * STAGE_B;
        #pragma unroll
        for (int r2 = 0; r2 < 4; r2++) {          // A tiles: 128 rows x 8 chunks
            int idx = tid + r2 * 256;
            int row = idx >> 3, ck = idx & 7;
            uint32_t so = (uint32_t)(row * 128 + ((ck ^ (row & 7)) << 4));
            cp_async16(st + OFF_AH + so, ah + row * DM + ck * 8);
            cp_async16(st + OFF_AL + so, al + row * DM + ck * 8);
        }
        #pragma unroll
        for (int r2 = 0; r2 < 2; r2++) {          // B tiles: 64 rows x 8 chunks
            int idx = tid + r2 * 256;
            int row = idx >> 3, ck = idx & 7;
            uint32_t so = (uint32_t)(row * 128 + ((ck ^ (row & 7)) << 4));
            cp_async16(st + OFF_BH + so, bh + row * DM + ck * 8);
            cp_async16(st + OFF_BL + so, bl + row * DM + ck * 8);
        }
        asm volatile("cp.async.commit_group;");
    };

    load_chunk(0, 0);

    for (int it = 0; it < NCHUNK; it++) {
        if (it + 1 < NCHUNK) {
            load_chunk(it + 1, (it + 1) & 1);
            asm volatile("cp.async.wait_group 1;");
        } else {
            asm volatile("cp.async.wait_group 0;");
        }
        __syncthreads();

        uint32_t st = sb + (it & 1) * STAGE_B;

        #pragma unroll
        for (int kq = 0; kq < 4; kq++) {
            int k16 = (kq + kphase) & 3;          // warp-group phase rotation
            int kc = k16 * 16;
            uint32_t ah[2][4], al[2][4];
            #pragma unroll
            for (int mi = 0; mi < 2; mi++) {
                int row = wm * 32 + mi * 16 + (lane & 7) + ((lane >> 3) & 1) * 8;
                int kk  = kc + ((lane >> 4) << 3);
                uint32_t so = sw_off(row, kk);
                ldmatrix_x4(ah[mi][0], ah[mi][1], ah[mi][2], ah[mi][3], st + OFF_AH + so);
                ldmatrix_x4(al[mi][0], al[mi][1], al[mi][2], al[mi][3], st + OFF_AL + so);
            }
            uint32_t bh[2][4], bl[2][4];
            #pragma unroll
            for (int nb = 0; nb < 2; nb++) {
                int row = wn * 32 + nb * 16 + (lane & 7) + ((lane >> 4) << 3);
                int kk  = kc + (((lane >> 3) & 1) << 3);
                uint32_t so = sw_off(row, kk);
                ldmatrix_x4(bh[nb][0], bh[nb][1], bh[nb][2], bh[nb][3], st + OFF_BH + so);
                ldmatrix_x4(bl[nb][0], bl[nb][1], bl[nb][2], bl[nb][3], st + OFF_BL + so);
            }
            #pragma unroll
            for (int mi = 0; mi < 2; mi++)            // hi*hi
                #pragma unroll
                for (int nb = 0; nb < 2; nb++)
                    #pragma unroll
                    for (int h = 0; h < 2; h++)
                        mma16816(acc[mi][nb * 2 + h], ah[mi], bh[nb][2 * h], bh[nb][2 * h + 1]);
            #pragma unroll
            for (int mi = 0; mi < 2; mi++)            // hi*lo
                #pragma unroll
                for (int nb = 0; nb < 2; nb++)
                    #pragma unroll
                    for (int h = 0; h < 2; h++)
                        mma16816(acc[mi][nb * 2 + h], ah[mi], bl[nb][2 * h], bl[nb][2 * h + 1]);
            #pragma unroll
            for (int mi = 0; mi < 2; mi++)            // lo*hi
                #pragma unroll
                for (int nb = 0; nb < 2; nb++)
                    #pragma unroll
                    for (int h = 0; h < 2; h++)
                        mma16816(acc[mi][nb * 2 + h], al[mi], bh[nb][2 * h], bh[nb][2 * h + 1]);
        }
        __syncthreads();
    }

    // epilogue
    int qr = lane >> 2, qc = (lane & 3) << 1;
    #pragma unroll
    for (int mi = 0; mi < 2; mi++) {
        int r0 = m0 + wm * 32 + mi * 16 + qr;
        #pragma unroll
        for (int ni = 0; ni < 4; ni++) {
            int c = n0 + wn * 32 + ni * 8 + qc;
            float* o0 = out + ((size_t)b * SEQ + r0) * DM + c;
            float* o1 = o0 + 8 * DM;
            *reinterpret_cast<float2*>(o0) = make_float2(acc[mi][ni][0], acc[mi][ni][1]);
            *reinterpret_cast<float2*>(o1) = make_float2(acc[mi][ni][2], acc[mi][ni][3]);
        }
    }
}

// ============================ launch ============================
extern "C" void kernel_launch(void* const* d_in, const int* in_sizes, int n_in,
                              void* d_out, int out_size) {
    const float* q = (const float*)d_in[0];
    const float* k = (const float*)d_in[1];
    const float* e = (const float*)d_in[2];
    float* out = (float*)d_out;

    cudaFuncSetAttribute(rel_gemm_kernel,
                         cudaFuncAttributeMaxDynamicSharedMemorySize, SMEM_TOTAL);

    prep_all_kernel<<<QBLOCKS + KBLOCKS + EBLOCKS, 128>>>(q, k, e);
    rel_gemm_kernel<<<dim3(SEQ / BN, SEQ / BM, BATCH), 256, SMEM_TOTAL>>>(out);
}

// round 8
// speedup vs baseline: 1.0006x; 1.0006x over previous
#include <cuda_runtime.h>
#include <cuda_bf16.h>
#include <cstdint>

#define BATCH 8
#define SEQ 512
#define DM 512
#define NELEM (BATCH*SEQ*DM)

// ============================ scratch (bf16 hi/lo splits) ============================
__device__ __align__(16) __nv_bfloat16 g_Qhi[NELEM];
__device__ __align__(16) __nv_bfloat16 g_Qlo[NELEM];
__device__ __align__(16) __nv_bfloat16 g_QRhi[NELEM];
__device__ __align__(16) __nv_bfloat16 g_QRlo[NELEM];
__device__ __align__(16) __nv_bfloat16 g_Khi[NELEM];
__device__ __align__(16) __nv_bfloat16 g_Klo[NELEM];
__device__ __align__(16) __nv_bfloat16 g_Ethi[DM*DM];
__device__ __align__(16) __nv_bfloat16 g_Etlo[DM*DM];

__device__ __forceinline__ void split_bf16(float x, __nv_bfloat16& h, __nv_bfloat16& l) {
    h = __float2bfloat16(x);
    l = __float2bfloat16(x - __bfloat162float(h));
}

__device__ __forceinline__ uint32_t smem_u32(const void* p) {
    uint32_t a;
    asm("{ .reg .u64 t; cvta.to.shared.u64 t, %1; cvt.u32.u64 %0, t; }" : "=r"(a) : "l"(p));
    return a;
}

// ============================ fused prep kernel ============================
#define QBLOCKS (BATCH*SEQ)
#define KBLOCKS 2048
#define EBLOCKS 256

__global__ void prep_all_kernel(const float* __restrict__ q,
                                const float* __restrict__ k,
                                const float* __restrict__ e) {
    __shared__ float sh[32 * 33 + 128];
    int bid = blockIdx.x;
    int t = threadIdx.x;                  // 128 threads

    if (bid < QBLOCKS) {
        float* row = sh;
        float* red = sh + 512;
        int i = bid & (SEQ - 1);
        const float4* src = reinterpret_cast<const float4*>(q + (size_t)bid * DM);
        reinterpret_cast<float4*>(row)[t] = src[t];
        __syncthreads();

        float p = 0.f;
        #pragma unroll
        for (int j = t; j < DM; j += 128)
            if (j >= i) p += row[j];
        red[t] = p;
        __syncthreads();
        #pragma unroll
        for (int s = 64; s > 0; s >>= 1) {
            if (t < s) red[t] += red[t + s];
            __syncthreads();
        }
        float suf = red[0];

        size_t base = (size_t)bid * DM;
        #pragma unroll
        for (int d = t; d < DM; d += 128) {
            float x = row[d];
            split_bf16(x, g_Qhi[base + d], g_Qlo[base + d]);
            float r = (d == 0) ? suf : ((d <= i) ? row[i - d] : 0.f);
            split_bf16(r, g_QRhi[base + d], g_QRlo[base + d]);
        }
    } else if (bid < QBLOCKS + KBLOCKS) {
        int idx = (bid - QBLOCKS) * 128 + t;
        int n4 = NELEM / 4;
        int stride = KBLOCKS * 128;
        for (int j = idx; j < n4; j += stride) {
            float4 v = reinterpret_cast<const float4*>(k)[j];
            __nv_bfloat16 h[4], l[4];
            split_bf16(v.x, h[0], l[0]);
            split_bf16(v.y, h[1], l[1]);
            split_bf16(v.z, h[2], l[2]);
            split_bf16(v.w, h[3], l[3]);
            reinterpret_cast<uint2*>(g_Khi)[j] = *reinterpret_cast<uint2*>(h);
            reinterpret_cast<uint2*>(g_Klo)[j] = *reinterpret_cast<uint2*>(l);
        }
    } else {
        float (*tile)[33] = reinterpret_cast<float(*)[33]>(sh);
        int eb = bid - QBLOCKS - KBLOCKS;
        int bx = eb & 15, by = eb >> 4;
        int tx = t & 31, j0 = t >> 5;
        #pragma unroll
        for (int j = j0; j < 32; j += 4)
            tile[j][tx] = e[(size_t)(by * 32 + j) * DM + bx * 32 + tx];
        __syncthreads();
        #pragma unroll
        for (int j = j0; j < 32; j += 4) {
            size_t o = (size_t)(bx * 32 + j) * DM + by * 32 + tx;
            split_bf16(tile[tx][j], g_Ethi[o], g_Etlo[o]);
        }
    }
}

// ============================ main GEMM (mma.sync bf16, term-shared) ============================
// out[b,i,n] = Qhi.Khi + Qhi.Klo + Qlo.Khi  +  QRhi.Ethi + QRhi.Etlo + QRlo.Ethi
// Pass 1 (Qrev.Et) skips K-chunks that are entirely zero (Qrev[i,d]=0 for d>i):
// an M-tile at m0=128*by only needs 2*by+2 of the 8 chunks.

#define BM 128
#define BN 64
#define BK 64
#define AT_B (BM * BK * 2)                  // 16384 per A tile
#define BT_B (BN * BK * 2)                  // 8192 per B tile
#define STAGE_B (2 * AT_B + 2 * BT_B)       // 49152
#define SMEM_TOTAL (2 * STAGE_B)            // 98304 (2 stages), 2 CTAs/SM

#define OFF_AH 0
#define OFF_AL AT_B
#define OFF_BH (2 * AT_B)
#define OFF_BL (2 * AT_B + BT_B)

__device__ __forceinline__ uint32_t sw_off(int row, int kk) {
    return (uint32_t)(row * 128 + (((kk >> 3) ^ (row & 7)) << 4) + ((kk & 7) << 1));
}

__device__ __forceinline__ void cp_async16(uint32_t saddr, const void* gaddr) {
    asm volatile("cp.async.cg.shared.global [%0], [%1], 16;" :: "r"(saddr), "l"(gaddr));
}

__device__ __forceinline__ void ldmatrix_x4(uint32_t& r0, uint32_t& r1, uint32_t& r2,
                                            uint32_t& r3, uint32_t addr) {
    asm volatile("ldmatrix.sync.aligned.m8n8.x4.shared.b16 {%0,%1,%2,%3}, [%4];"
                 : "=r"(r0), "=r"(r1), "=r"(r2), "=r"(r3) : "r"(addr));
}

__device__ __forceinline__ void mma16816(float* c, const uint32_t* a, uint32_t b0, uint32_t b1) {
    asm volatile(
        "mma.sync.aligned.m16n8k16.row.col.f32.bf16.bf16.f32 "
        "{%0,%1,%2,%3}, {%4,%5,%6,%7}, {%8,%9}, {%0,%1,%2,%3};"
        : "+f"(c[0]), "+f"(c[1]), "+f"(c[2]), "+f"(c[3])
        : "r"(a[0]), "r"(a[1]), "r"(a[2]), "r"(a[3]), "r"(b0), "r"(b1));
}

__global__ __launch_bounds__(256, 2) void rel_gemm_kernel(float* __restrict__ out) {
    extern __shared__ char smem[];
    uint32_t sb = smem_u32(smem);

    int tid = threadIdx.x;
    int lane = tid & 31, wid = tid >> 5;
    int wm = wid & 3, wn = wid >> 2;          // 4 m-warps x 2 n-warps, warp tile 32x32
    int n0 = blockIdx.x * BN;
    int m0 = blockIdx.y * BM;
    int b  = blockIdx.z;
    size_t boff = (size_t)b * SEQ * DM;

    // chunks: [0,8) pass 0 (Q.K), [8, 8+2*by+2) pass 1 (Qrev.Et, nonzero prefix only)
    int total = 10 + 2 * (int)blockIdx.y;

    const __nv_bfloat16* AH[2] = { g_Qhi + boff, g_QRhi + boff };
    const __nv_bfloat16* AL[2] = { g_Qlo + boff, g_QRlo + boff };
    const __nv_bfloat16* BH[2] = { g_Khi + boff, g_Ethi };
    const __nv_bfloat16* BL[2] = { g_Klo + boff, g_Etlo };

    float acc[2][4][4];
    #pragma unroll
    for (int mi = 0; mi < 2; mi++)
        #pragma unroll
        for (int ni = 0; ni < 4; ni++)
            #pragma unroll
            for (int j = 0; j < 4; j++) acc[mi][ni][j] = 0.f;

    auto load_chunk = [&](int it, int buf) {
        int pass = it >> 3, kc = it & 7;
        const __nv_bfloat16* ah = AH[pass] + (size_t)m0 * DM + kc * BK;
        const __nv_bfloat16* al = AL[pass] + (size_t)m0 * DM + kc * BK;
        const __nv_bfloat16* bh = BH[pass] + (size_t)n0 * DM + kc * BK;
        const __nv_bfloat16* bl = BL[pass] + (size_t)n0 * DM + kc * BK;
        uint32_t st = sb + buf * STAGE_B;
        #pragma unroll
        for (int r2 = 0; r2 < 4; r2++) {          // A tiles: 128 rows x 8 chunks
            int idx = tid + r2 * 256;
            int row = idx >> 3, ck = idx & 7;
            uint32_t so = (uint32_t)(row * 128 + ((ck ^ (row & 7)) << 4));
            cp_async16(st + OFF_AH + so, ah + row * DM + ck * 8);
            cp_async16(st + OFF_AL + so, al + row * DM + ck * 8);
        }
        #pragma unroll
        for (int r2 = 0; r2 < 2; r2++) {          // B tiles: 64 rows x 8 chunks
            int idx = tid + r2 * 256;
            int row = idx >> 3, ck = idx & 7;
            uint32_t so = (uint32_t)(row * 128 + ((ck ^ (row & 7)) << 4));
            cp_async16(st + OFF_BH + so, bh + row * DM + ck * 8);
            cp_async16(st + OFF_BL + so, bl + row * DM + ck * 8);
        }
        asm volatile("cp.async.commit_group;");
    };

    load_chunk(0, 0);

    for (int it = 0; it < total; it++) {
        // exactly one group pending here: load(it)
        asm volatile("cp.async.wait_group 0;");
        __syncthreads();   // also separates compute(it-1) from overwrite below
        if (it + 1 < total) load_chunk(it + 1, (it + 1) & 1);

        uint32_t st = sb + (it & 1) * STAGE_B;

        #pragma unroll
        for (int k16 = 0; k16 < 4; k16++) {
            int kc = k16 * 16;
            uint32_t ah[2][4], al[2][4];
            #pragma unroll
            for (int mi = 0; mi < 2; mi++) {
                int row = wm * 32 + mi * 16 + (lane & 7) + ((lane >> 3) & 1) * 8;
                int kk  = kc + ((lane >> 4) << 3);
                uint32_t so = sw_off(row, kk);
                ldmatrix_x4(ah[mi][0], ah[mi][1], ah[mi][2], ah[mi][3], st + OFF_AH + so);
                ldmatrix_x4(al[mi][0], al[mi][1], al[mi][2], al[mi][3], st + OFF_AL + so);
            }
            uint32_t bh[2][4], bl[2][4];
            #pragma unroll
            for (int nb = 0; nb < 2; nb++) {
                int row = wn * 32 + nb * 16 + (lane & 7) + ((lane >> 4) << 3);
                int kk  = kc + (((lane >> 3) & 1) << 3);
                uint32_t so = sw_off(row, kk);
                ldmatrix_x4(bh[nb][0], bh[nb][1], bh[nb][2], bh[nb][3], st + OFF_BH + so);
                ldmatrix_x4(bl[nb][0], bl[nb][1], bl[nb][2], bl[nb][3], st + OFF_BL + so);
            }
            #pragma unroll
            for (int mi = 0; mi < 2; mi++)            // hi*hi
                #pragma unroll
                for (int nb = 0; nb < 2; nb++)
                    #pragma unroll
                    for (int h = 0; h < 2; h++)
                        mma16816(acc[mi][nb * 2 + h], ah[mi], bh[nb][2 * h], bh[nb][2 * h + 1]);
            #pragma unroll
            for (int mi = 0; mi < 2; mi++)            // hi*lo
                #pragma unroll
                for (int nb = 0; nb < 2; nb++)
                    #pragma unroll
                    for (int h = 0; h < 2; h++)
                        mma16816(acc[mi][nb * 2 + h], ah[mi], bl[nb][2 * h], bl[nb][2 * h + 1]);
            #pragma unroll
            for (int mi = 0; mi < 2; mi++)            // lo*hi
                #pragma unroll
                for (int nb = 0; nb < 2; nb++)
                    #pragma unroll
                    for (int h = 0; h < 2; h++)
                        mma16816(acc[mi][nb * 2 + h], al[mi], bh[nb][2 * h], bh[nb][2 * h + 1]);
        }
    }

    // epilogue
    int qr = lane >> 2, qc = (lane & 3) << 1;
    #pragma unroll
    for (int mi = 0; mi < 2; mi++) {
        int r0 = m0 + wm * 32 + mi * 16 + qr;
        #pragma unroll
        for (int ni = 0; ni < 4; ni++) {
            int c = n0 + wn * 32 + ni * 8 + qc;
            float* o0 = out + ((size_t)b * SEQ + r0) * DM + c;
            float* o1 = o0 + 8 * DM;
            *reinterpret_cast<float2*>(o0) = make_float2(acc[mi][ni][0], acc[mi][ni][1]);
            *reinterpret_cast<float2*>(o1) = make_float2(acc[mi][ni][2], acc[mi][ni][3]);
        }
    }
}

// ============================ launch ============================
extern "C" void kernel_launch(void* const* d_in, const int* in_sizes, int n_in,
                              void* d_out, int out_size) {
    const float* q = (const float*)d_in[0];
    const float* k = (const float*)d_in[1];
    const float* e = (const float*)d_in[2];
    float* out = (float*)d_out;

    cudaFuncSetAttribute(rel_gemm_kernel,
                         cudaFuncAttributeMaxDynamicSharedMemorySize, SMEM_TOTAL);

    prep_all_kernel<<<QBLOCKS + KBLOCKS + EBLOCKS, 128>>>(q, k, e);
    rel_gemm_kernel<<<dim3(SEQ / BN, SEQ / BM, BATCH), 256, SMEM_TOTAL>>>(out);
}

// round 10
// speedup vs baseline: 1.0013x; 1.0006x over previous
#include <cuda_runtime.h>
#include <cuda_bf16.h>
#include <cstdint>

#define BATCH 8
#define SEQ 512
#define DM 512
#define NELEM (BATCH*SEQ*DM)

// ============================ scratch (bf16 hi/lo splits) ============================
__device__ __align__(16) __nv_bfloat16 g_Qhi[NELEM];
__device__ __align__(16) __nv_bfloat16 g_Qlo[NELEM];
__device__ __align__(16) __nv_bfloat16 g_QRhi[NELEM];
__device__ __align__(16) __nv_bfloat16 g_QRlo[NELEM];
__device__ __align__(16) __nv_bfloat16 g_Khi[NELEM];
__device__ __align__(16) __nv_bfloat16 g_Klo[NELEM];
__device__ __align__(16) __nv_bfloat16 g_Ethi[DM*DM];
__device__ __align__(16) __nv_bfloat16 g_Etlo[DM*DM];

__device__ __forceinline__ void split_bf16(float x, __nv_bfloat16& h, __nv_bfloat16& l) {
    h = __float2bfloat16(x);
    l = __float2bfloat16(x - __bfloat162float(h));
}

__device__ __forceinline__ uint32_t smem_u32(const void* p) {
    uint32_t a;
    asm("{ .reg .u64 t; cvta.to.shared.u64 t, %1; cvt.u32.u64 %0, t; }" : "=r"(a) : "l"(p));
    return a;
}

// ============================ fused prep kernel ============================
#define QBLOCKS (BATCH*SEQ)
#define KBLOCKS 2048
#define EBLOCKS 256

__global__ void prep_all_kernel(const float* __restrict__ q,
                                const float* __restrict__ k,
                                const float* __restrict__ e) {
    __shared__ float sh[32 * 33 + 128];
    int bid = blockIdx.x;
    int t = threadIdx.x;                  // 128 threads

    if (bid < QBLOCKS) {
        float* row = sh;
        float* red = sh + 512;
        int i = bid & (SEQ - 1);
        const float4* src = reinterpret_cast<const float4*>(q + (size_t)bid * DM);
        reinterpret_cast<float4*>(row)[t] = src[t];
        __syncthreads();

        float p = 0.f;
        #pragma unroll
        for (int j = t; j < DM; j += 128)
            if (j >= i) p += row[j];
        red[t] = p;
        __syncthreads();
        #pragma unroll
        for (int s = 64; s > 0; s >>= 1) {
            if (t < s) red[t] += red[t + s];
            __syncthreads();
        }
        float suf = red[0];

        size_t base = (size_t)bid * DM;
        #pragma unroll
        for (int d = t; d < DM; d += 128) {
            float x = row[d];
            split_bf16(x, g_Qhi[base + d], g_Qlo[base + d]);
            float r = (d == 0) ? suf : ((d <= i) ? row[i - d] : 0.f);
            split_bf16(r, g_QRhi[base + d], g_QRlo[base + d]);
        }
    } else if (bid < QBLOCKS + KBLOCKS) {
        int idx = (bid - QBLOCKS) * 128 + t;
        int n4 = NELEM / 4;
        int stride = KBLOCKS * 128;
        for (int j = idx; j < n4; j += stride) {
            float4 v = reinterpret_cast<const float4*>(k)[j];
            __nv_bfloat16 h[4], l[4];
            split_bf16(v.x, h[0], l[0]);
            split_bf16(v.y, h[1], l[1]);
            split_bf16(v.z, h[2], l[2]);
            split_bf16(v.w, h[3], l[3]);
            reinterpret_cast<uint2*>(g_Khi)[j] = *reinterpret_cast<uint2*>(h);
            reinterpret_cast<uint2*>(g_Klo)[j] = *reinterpret_cast<uint2*>(l);
        }
    } else {
        float (*tile)[33] = reinterpret_cast<float(*)[33]>(sh);
        int eb = bid - QBLOCKS - KBLOCKS;
        int bx = eb & 15, by = eb >> 4;
        int tx = t & 31, j0 = t >> 5;
        #pragma unroll
        for (int j = j0; j < 32; j += 4)
            tile[j][tx] = e[(size_t)(by * 32 + j) * DM + bx * 32 + tx];
        __syncthreads();
        #pragma unroll
        for (int j = j0; j < 32; j += 4) {
            size_t o = (size_t)(bx * 32 + j) * DM + by * 32 + tx;
            split_bf16(tile[tx][j], g_Ethi[o], g_Etlo[o]);
        }
    }
}

// ============================ main GEMM (mma.sync bf16) ============================
// 128x128 CTA tile, 512 threads (4x4 warps, 32x32 warp tiles), 3-stage cp.async.
// Pass 1 (Qrev.Et) skips all-zero K-chunks: tile at m0=128*by needs 2*by+2 of 8.

#define BM 128
#define BN 128
#define BK 64
#define THREADS 512
#define TILE_HB (BM * BK * 2)               // 16384 per hi or lo tile (A and B same)
#define STAGE_B (4 * TILE_HB)               // 65536: Ahi,Alo,Bhi,Blo
#define NSTAGE 3
#define SMEM_TOTAL (NSTAGE * STAGE_B)       // 196608

#define OFF_AH 0
#define OFF_AL TILE_HB
#define OFF_BH (2 * TILE_HB)
#define OFF_BL (3 * TILE_HB)

__device__ __forceinline__ uint32_t sw_off(int row, int kk) {
    return (uint32_t)(row * 128 + (((kk >> 3) ^ (row & 7)) << 4) + ((kk & 7) << 1));
}

__device__ __forceinline__ void cp_async16(uint32_t saddr, const void* gaddr) {
    asm volatile("cp.async.cg.shared.global [%0], [%1], 16;" :: "r"(saddr), "l"(gaddr));
}

__device__ __forceinline__ void ldmatrix_x4(uint32_t& r0, uint32_t& r1, uint32_t& r2,
                                            uint32_t& r3, uint32_t addr) {
    asm volatile("ldmatrix.sync.aligned.m8n8.x4.shared.b16 {%0,%1,%2,%3}, [%4];"
                 : "=r"(r0), "=r"(r1), "=r"(r2), "=r"(r3) : "r"(addr));
}

__device__ __forceinline__ void mma16816(float* c, const uint32_t* a, uint32_t b0, uint32_t b1) {
    asm volatile(
        "mma.sync.aligned.m16n8k16.row.col.f32.bf16.bf16.f32 "
        "{%0,%1,%2,%3}, {%4,%5,%6,%7}, {%8,%9}, {%0,%1,%2,%3};"
        : "+f"(c[0]), "+f"(c[1]), "+f"(c[2]), "+f"(c[3])
        : "r"(a[0]), "r"(a[1]), "r"(a[2]), "r"(a[3]), "r"(b0), "r"(b1));
}

__global__ __launch_bounds__(THREADS, 1) void rel_gemm_kernel(float* __restrict__ out) {
    extern __shared__ char smem[];
    uint32_t sb = smem_u32(smem);

    int tid = threadIdx.x;
    int lane = tid & 31, wid = tid >> 5;
    int wm = wid & 3, wn = wid >> 2;          // 4 m-warps x 4 n-warps, warp tile 32x32
    int n0 = blockIdx.x * BN;
    int m0 = blockIdx.y * BM;
    int b  = blockIdx.z;
    size_t boff = (size_t)b * SEQ * DM;

    // chunks: [0,8) pass 0 (Q.K), [8, 10+2*by) pass 1 (Qrev.Et nonzero prefix)
    int total = 10 + 2 * (int)blockIdx.y;

    const __nv_bfloat16* AH[2] = { g_Qhi + boff, g_QRhi + boff };
    const __nv_bfloat16* AL[2] = { g_Qlo + boff, g_QRlo + boff };
    const __nv_bfloat16* BH[2] = { g_Khi + boff, g_Ethi };
    const __nv_bfloat16* BL[2] = { g_Klo + boff, g_Etlo };

    float acc[2][4][4];
    #pragma unroll
    for (int mi = 0; mi < 2; mi++)
        #pragma unroll
        for (int ni = 0; ni < 4; ni++)
            #pragma unroll
            for (int j = 0; j < 4; j++) acc[mi][ni][j] = 0.f;

    auto load_chunk = [&](int it) {
        int pass = it >> 3, kc = it & 7;
        const __nv_bfloat16* ah = AH[pass] + (size_t)m0 * DM + kc * BK;
        const __nv_bfloat16* al = AL[pass] + (size_t)m0 * DM + kc * BK;
        const __nv_bfloat16* bh = BH[pass] + (size_t)n0 * DM + kc * BK;
        const __nv_bfloat16* bl = BL[pass] + (size_t)n0 * DM + kc * BK;
        uint32_t st = sb + (it % NSTAGE) * STAGE_B;
        #pragma unroll
        for (int r2 = 0; r2 < 2; r2++) {          // 128 rows x 8 16B-chunks = 1024
            int idx = tid + r2 * THREADS;
            int row = idx >> 3, ck = idx & 7;
            uint32_t so = (uint32_t)(row * 128 + ((ck ^ (row & 7)) << 4));
            cp_async16(st + OFF_AH + so, ah + row * DM + ck * 8);
            cp_async16(st + OFF_AL + so, al + row * DM + ck * 8);
            cp_async16(st + OFF_BH + so, bh + row * DM + ck * 8);
            cp_async16(st + OFF_BL + so, bl + row * DM + ck * 8);
        }
        asm volatile("cp.async.commit_group;");
    };

    load_chunk(0);
    if (total > 1) load_chunk(1);

    for (int it = 0; it < total; it++) {
        asm volatile("cp.async.wait_group 1;");   // load(it) complete; load(it+1) may pend
        __syncthreads();                          // all warps done with stage (it+2)%NSTAGE
        if (it + 2 < total) load_chunk(it + 2);

        uint32_t st = sb + (it % NSTAGE) * STAGE_B;

        #pragma unroll
        for (int k16 = 0; k16 < 4; k16++) {
            int kc = k16 * 16;
            uint32_t ah[2][4], al[2][4];
            #pragma unroll
            for (int mi = 0; mi < 2; mi++) {
                int row = wm * 32 + mi * 16 + (lane & 7) + ((lane >> 3) & 1) * 8;
                int kk  = kc + ((lane >> 4) << 3);
                uint32_t so = sw_off(row, kk);
                ldmatrix_x4(ah[mi][0], ah[mi][1], ah[mi][2], ah[mi][3], st + OFF_AH + so);
                ldmatrix_x4(al[mi][0], al[mi][1], al[mi][2], al[mi][3], st + OFF_AL + so);
            }
            uint32_t bh[2][4], bl[2][4];
            #pragma unroll
            for (int nb = 0; nb < 2; nb++) {
                int row = wn * 32 + nb * 16 + (lane & 7) + ((lane >> 4) << 3);
                int kk  = kc + (((lane >> 3) & 1) << 3);
                uint32_t so = sw_off(row, kk);
                ldmatrix_x4(bh[nb][0], bh[nb][1], bh[nb][2], bh[nb][3], st + OFF_BH + so);
                ldmatrix_x4(bl[nb][0], bl[nb][1], bl[nb][2], bl[nb][3], st + OFF_BL + so);
            }
            #pragma unroll
            for (int mi = 0; mi < 2; mi++)            // hi*hi
                #pragma unroll
                for (int nb = 0; nb < 2; nb++)
                    #pragma unroll
                    for (int h = 0; h < 2; h++)
                        mma16816(acc[mi][nb * 2 + h], ah[mi], bh[nb][2 * h], bh[nb][2 * h + 1]);
            #pragma unroll
            for (int mi = 0; mi < 2; mi++)            // hi*lo
                #pragma unroll
                for (int nb = 0; nb < 2; nb++)
                    #pragma unroll
                    for (int h = 0; h < 2; h++)
                        mma16816(acc[mi][nb * 2 + h], ah[mi], bl[nb][2 * h], bl[nb][2 * h + 1]);
            #pragma unroll
            for (int mi = 0; mi < 2; mi++)            // lo*hi
                #pragma unroll
                for (int nb = 0; nb < 2; nb++)
                    #pragma unroll
                    for (int h = 0; h < 2; h++)
                        mma16816(acc[mi][nb * 2 + h], al[mi], bh[nb][2 * h], bh[nb][2 * h + 1]);
        }
    }

    // epilogue
    int qr = lane >> 2, qc = (lane & 3) << 1;
    #pragma unroll
    for (int mi = 0; mi < 2; mi++) {
        int r0 = m0 + wm * 32 + mi * 16 + qr;
        #pragma unroll
        for (int ni = 0; ni < 4; ni++) {
            int c = n0 + wn * 32 + ni * 8 + qc;
            float* o0 = out + ((size_t)b * SEQ + r0) * DM + c;
            float* o1 = o0 + 8 * DM;
            *reinterpret_cast<float2*>(o0) = make_float2(acc[mi][ni][0], acc[mi][ni][1]);
            *reinterpret_cast<float2*>(o1) = make_float2(acc[mi][ni][2], acc[mi][ni][3]);
        }
    }
}

// ============================ launch ============================
extern "C" void kernel_launch(void* const* d_in, const int* in_sizes, int n_in,
                              void* d_out, int out_size) {
    const float* q = (const float*)d_in[0];
    const float* k = (const float*)d_in[1];
    const float* e = (const float*)d_in[2];
    float* out = (float*)d_out;

    cudaFuncSetAttribute(rel_gemm_kernel,
                         cudaFuncAttributeMaxDynamicSharedMemorySize, SMEM_TOTAL);

    prep_all_kernel<<<QBLOCKS + KBLOCKS + EBLOCKS, 128>>>(q, k, e);
    rel_gemm_kernel<<<dim3(SEQ / BN, SEQ / BM, BATCH), THREADS, SMEM_TOTAL>>>(out);
}